// round 6
// baseline (speedup 1.0000x reference)
#include <cuda_runtime.h>
#include <cuda_fp16.h>
#include <cstdint>

#define D_MODEL 1024
#define NQ      1024
#define NKV     4096
#define BATCH   4
#define NHEADS  16
#define HDIM    64

// ---------------- scratch (device globals: allocation-free) ----------------
__device__ float g_qp[(size_t)BATCH * NQ  * D_MODEL];   // 16 MB
__device__ float g_k [(size_t)BATCH * NKV * D_MODEL];   // 64 MB
__device__ float g_v [(size_t)BATCH * NKV * D_MODEL];   // 64 MB
__device__ float g_x [(size_t)BATCH * NQ  * D_MODEL];   // 16 MB
__device__ int   g_mask_is_i32;

// ---------------- helpers ----------------
__device__ __forceinline__ uint32_t f2h2(float lo, float hi) {
    __half2 h = __floats2half2_rn(lo, hi);
    return *(uint32_t*)&h;
}
__device__ __forceinline__ void mma_f16(float* c, const uint32_t* a,
                                        const uint32_t* b) {
    asm volatile(
        "mma.sync.aligned.m16n8k16.row.col.f32.f16.f16.f32 "
        "{%0,%1,%2,%3}, {%4,%5,%6,%7}, {%8,%9}, {%0,%1,%2,%3};"
        : "+f"(c[0]), "+f"(c[1]), "+f"(c[2]), "+f"(c[3])
        : "r"(a[0]), "r"(a[1]), "r"(a[2]), "r"(a[3]), "r"(b[0]), "r"(b[1]));
}
__device__ __forceinline__ uint32_t smem_u32(const void* p) {
    uint32_t a;
    asm("{ .reg .u64 t; cvta.to.shared.u64 t, %1; cvt.u32.u64 %0, t; }"
        : "=r"(a) : "l"(p));
    return a;
}
__device__ __forceinline__ void ldsm4(uint32_t* d, uint32_t addr) {
    asm volatile(
        "ldmatrix.sync.aligned.m8n8.x4.shared.b16 {%0,%1,%2,%3}, [%4];"
        : "=r"(d[0]), "=r"(d[1]), "=r"(d[2]), "=r"(d[3]) : "r"(addr));
}

// ---------------- mask dtype detector ----------------
__global__ void detect_mask_kernel(const unsigned int* __restrict__ w) {
    __shared__ int bad;
    if (threadIdx.x == 0) bad = 0;
    __syncthreads();
    for (int i = threadIdx.x; i < 4096; i += 256)
        if (w[i] > 1u) bad = 1;
    __syncthreads();
    if (threadIdx.x == 0) g_mask_is_i32 = !bad;
}

// ---------------- fp16 mma.sync GEMM: 128x128 tile, K-chunk 32 -------------
// A [m][k] halfs; B stored N-major [n][k] halfs. All frags via ldmatrix.
#define LDH 40

__global__ __launch_bounds__(256, 3) void sgemm_mma(
    const float* __restrict__ A, const float* __restrict__ B,
    float* __restrict__ C0, float* __restrict__ C1,
    int M, int N, int K, float alpha, const float* __restrict__ bias, int splitN)
{
    __shared__ __align__(16) __half As[128][LDH];
    __shared__ __align__(16) __half Bsn[128][LDH];

    const int tid = threadIdx.x;
    const int w   = tid >> 5;
    const int lane = tid & 31;
    const int warpM = w >> 2;
    const int warpN = w & 3;
    const int bm = blockIdx.y * 128;
    const int bn = blockIdx.x * 128;

    const int r8 = tid >> 3;
    const int f8 = tid & 7;

    const uint32_t sbA = smem_u32(As);
    const uint32_t sbB = smem_u32(Bsn);

    const int lr   = lane & 7;
    const int lhi8 = ((lane >> 4) & 1) * 8;
    const int lhf  = (lane >> 3) & 1;
    uint32_t aoff[4], boff[2];
#pragma unroll
    for (int mt = 0; mt < 4; mt++)
        aoff[mt] = sbA + ((warpM * 64 + mt * 16 + (lane & 15)) * LDH +
                          (lane >> 4) * 8) * 2;
#pragma unroll
    for (int nt2 = 0; nt2 < 2; nt2++)
        boff[nt2] = sbB + ((warpN * 32 + nt2 * 16 + lhi8 + lr) * LDH +
                           lhf * 8) * 2;

    float acc[4][4][4];
#pragma unroll
    for (int mt = 0; mt < 4; mt++)
#pragma unroll
        for (int nt = 0; nt < 4; nt++)
#pragma unroll
            for (int i = 0; i < 4; i++) acc[mt][nt][i] = 0.0f;

    const int bn_n = tid & 127;
    const int kq_b = tid >> 7;

    for (int k0 = 0; k0 < K; k0 += 32) {
        float4 av[4];
#pragma unroll
        for (int p = 0; p < 4; p++)
            av[p] = *(const float4*)(A + (size_t)(bm + p * 32 + r8) * K + k0 + f8 * 4);
        float bld[4][4];
#pragma unroll
        for (int it = 0; it < 4; it++) {
            const int kk = (2 * it + kq_b) * 4;
            const float* Bp = B + (size_t)(k0 + kk) * N + bn + bn_n;
#pragma unroll
            for (int c = 0; c < 4; c++)
                bld[it][c] = Bp[(size_t)c * N];
        }

        __syncthreads();
#pragma unroll
        for (int p = 0; p < 4; p++) {
            uint2 hv;
            hv.x = f2h2(av[p].x, av[p].y);
            hv.y = f2h2(av[p].z, av[p].w);
            *(uint2*)&As[p * 32 + r8][f8 * 4] = hv;
        }
#pragma unroll
        for (int it = 0; it < 4; it++) {
            const int kk = (2 * it + kq_b) * 4;
            uint2 hv;
            hv.x = f2h2(bld[it][0], bld[it][1]);
            hv.y = f2h2(bld[it][2], bld[it][3]);
            *(uint2*)&Bsn[bn_n][kk] = hv;
        }
        __syncthreads();

#pragma unroll
        for (int ks = 0; ks < 2; ks++) {
            const int kb = ks * 32;   // 16 halfs in bytes
            uint32_t af[4][4];
#pragma unroll
            for (int mt = 0; mt < 4; mt++)
                ldsm4(af[mt], aoff[mt] + kb);
#pragma unroll
            for (int nt2 = 0; nt2 < 2; nt2++) {
                uint32_t bf4[4];
                ldsm4(bf4, boff[nt2] + kb);
#pragma unroll
                for (int mt = 0; mt < 4; mt++) {
                    mma_f16(acc[mt][2 * nt2],     af[mt], &bf4[0]);
                    mma_f16(acc[mt][2 * nt2 + 1], af[mt], &bf4[2]);
                }
            }
        }
    }

    const int g = lane >> 2;
    const int t = lane & 3;
#pragma unroll
    for (int mt = 0; mt < 4; mt++) {
#pragma unroll
        for (int nt = 0; nt < 4; nt++) {
            const int row0 = bm + warpM * 64 + mt * 16 + g;
            const int col  = bn + warpN * 32 + nt * 8 + 2 * t;
            float2 v0, v1;
            v0.x = alpha * acc[mt][nt][0];
            v0.y = alpha * acc[mt][nt][1];
            v1.x = alpha * acc[mt][nt][2];
            v1.y = alpha * acc[mt][nt][3];
            if (bias) {
                const float bx = bias[col], by = bias[col + 1];
                v0.x += bx; v0.y += by;
                v1.x += bx; v1.y += by;
            }
            float* dst;
            int ld;
            int c = col;
            if (splitN && col >= splitN) {
                ld = N - splitN; c = col - splitN; dst = C1;
            } else {
                ld = splitN ? splitN : N; dst = C0;
            }
            *(float2*)(dst + (size_t)row0 * ld + c)       = v0;
            *(float2*)(dst + (size_t)(row0 + 8) * ld + c) = v1;
        }
    }
}

// ---------------- flash attention: fp16 mma + ldmatrix ---------------------
// CTA: 64 q-rows x head x batch; 4 warps x 16 q-rows. KV tile 64.
#define APH 72
#define ATT_SMEM (3 * 64 * APH * 2 + 64 * 4)

__global__ __launch_bounds__(128, 6) void attn_mma(
    const float* __restrict__ qp, const float* __restrict__ kmat,
    const float* __restrict__ vmat, const void* __restrict__ maskp,
    float* __restrict__ xout)
{
    extern __shared__ char smc[];
    __half* Kn = (__half*)smc;            // [kv=64][APH] native (d contiguous)
    __half* Vt = Kn + 64 * APH;           // [d=64][APH] transposed (kv contig)
    __half* Ps = Vt + 64 * APH;           // Q staging, then P [q=64][APH]
    float* mskb = (float*)(Ps + 64 * APH);

    const int tid = threadIdx.x;
    const int w = tid >> 5, lane = tid & 31;
    const int g = lane >> 2, t = lane & 3;
    const int q0 = blockIdx.x * 64;
    const int hh = blockIdx.y;
    const int b  = blockIdx.z;

    const uint32_t sbK = smem_u32(Kn);
    const uint32_t sbV = smem_u32(Vt);
    const uint32_t sbP = smem_u32(Ps);

    const float* qbase = qp   + ((size_t)b * NQ + q0) * D_MODEL + hh * HDIM;
    const float* kbase = kmat + (size_t)b * NKV * D_MODEL + hh * HDIM;
    const float* vbase = vmat + (size_t)b * NKV * D_MODEL + hh * HDIM;
    const int mi32 = g_mask_is_i32;
    const unsigned char* m8  = (const unsigned char*)maskp + (size_t)b * NKV;
    const int*           m32 = (const int*)maskp           + (size_t)b * NKV;

    const int lr   = lane & 7;
    const int lhi8 = ((lane >> 4) & 1) * 8;
    const int lhf  = (lane >> 3) & 1;
    uint32_t preB[4];
#pragma unroll
    for (int j2 = 0; j2 < 4; j2++)
        preB[j2] = ((j2 * 16 + lhi8 + lr) * APH + lhf * 8) * 2;
    const uint32_t preA = ((w * 16 + (lane & 15)) * APH + (lane >> 4) * 8) * 2;

    // stage Q tile (warp-private rows)
    {
        const int r = tid >> 1, c0 = (tid & 1) * 32;
        const float* src = qbase + (size_t)r * D_MODEL + c0;
        __half* dst = &Ps[r * APH + c0];
#pragma unroll
        for (int i = 0; i < 4; i++) {
            float4 v0 = *(const float4*)(src + 8 * i);
            float4 v1 = *(const float4*)(src + 8 * i + 4);
            uint4 hv;
            hv.x = f2h2(v0.x, v0.y); hv.y = f2h2(v0.z, v0.w);
            hv.z = f2h2(v1.x, v1.y); hv.w = f2h2(v1.z, v1.w);
            *(uint4*)(dst + 8 * i) = hv;
        }
    }
    __syncthreads();

    // preload Q fragments (4 k16-steps over d=64)
    const int mrow = w * 16 + g;
    uint32_t aq[4][4];
#pragma unroll
    for (int ks = 0; ks < 4; ks++)
        ldsm4(aq[ks], sbP + preA + ks * 32);

    float m_run[2] = {-1e30f, -1e30f};
    float l_run[2] = {0.0f, 0.0f};
    float o[8][4];
#pragma unroll
    for (int j = 0; j < 8; j++)
#pragma unroll
        for (int i = 0; i < 4; i++) o[j][i] = 0.0f;

    for (int k0 = 0; k0 < NKV; k0 += 64) {
        __syncthreads();  // prior tile fully consumed

        // K tile native [kv][d] (vectorized half stores)
        {
            const int r = tid >> 1, c0 = (tid & 1) * 32;
            const float* src = kbase + (size_t)(k0 + r) * D_MODEL + c0;
            __half* dst = &Kn[r * APH + c0];
#pragma unroll
            for (int i = 0; i < 4; i++) {
                float4 v0 = *(const float4*)(src + 8 * i);
                float4 v1 = *(const float4*)(src + 8 * i + 4);
                uint4 hv;
                hv.x = f2h2(v0.x, v0.y); hv.y = f2h2(v0.z, v0.w);
                hv.z = f2h2(v1.x, v1.y); hv.w = f2h2(v1.z, v1.w);
                *(uint4*)(dst + 8 * i) = hv;
            }
        }
        // V tile transposed [d][kv]: thread handles kv pair, 16 d values
        {
            const int kpair = (lane) * 2 + 0;  // within-warp kv pair base
            const int kp = (tid & 31) * 2;
            const int c0 = (tid >> 5) * 16;
            (void)kpair;
            const float* s0 = vbase + (size_t)(k0 + kp) * D_MODEL + c0;
            const float* s1 = s0 + D_MODEL;
#pragma unroll
            for (int i = 0; i < 4; i++) {
                float4 a = *(const float4*)(s0 + 4 * i);
                float4 c = *(const float4*)(s1 + 4 * i);
                const int d0 = c0 + 4 * i;
                *(uint32_t*)&Vt[(d0 + 0) * APH + kp] = f2h2(a.x, c.x);
                *(uint32_t*)&Vt[(d0 + 1) * APH + kp] = f2h2(a.y, c.y);
                *(uint32_t*)&Vt[(d0 + 2) * APH + kp] = f2h2(a.z, c.z);
                *(uint32_t*)&Vt[(d0 + 3) * APH + kp] = f2h2(a.w, c.w);
            }
        }
        // mask bias
        if (tid < 64) {
            const int kk = k0 + tid;
            const bool masked = mi32 ? (m32[kk] != 0) : (m8[kk] != 0);
            mskb[tid] = masked ? -1e30f : 0.0f;
        }
        __syncthreads();

        // S = Q K^T
        float s[8][4];
#pragma unroll
        for (int j = 0; j < 8; j++)
#pragma unroll
            for (int i = 0; i < 4; i++) s[j][i] = 0.0f;

#pragma unroll
        for (int ks = 0; ks < 4; ks++) {
            const int kb = ks * 32;
#pragma unroll
            for (int j2 = 0; j2 < 4; j2++) {
                uint32_t bf4[4];
                ldsm4(bf4, sbK + preB[j2] + kb);
                mma_f16(s[2 * j2],     aq[ks], &bf4[0]);
                mma_f16(s[2 * j2 + 1], aq[ks], &bf4[2]);
            }
        }

        // mask bias + online softmax (rows g and g+8)
        float rm0 = -1e30f, rm1 = -1e30f;
#pragma unroll
        for (int j = 0; j < 8; j++) {
            const float b0 = mskb[j * 8 + 2 * t];
            const float b1 = mskb[j * 8 + 2 * t + 1];
            s[j][0] += b0; s[j][1] += b1;
            s[j][2] += b0; s[j][3] += b1;
            rm0 = fmaxf(rm0, fmaxf(s[j][0], s[j][1]));
            rm1 = fmaxf(rm1, fmaxf(s[j][2], s[j][3]));
        }
        rm0 = fmaxf(rm0, __shfl_xor_sync(0xffffffffu, rm0, 1));
        rm0 = fmaxf(rm0, __shfl_xor_sync(0xffffffffu, rm0, 2));
        rm1 = fmaxf(rm1, __shfl_xor_sync(0xffffffffu, rm1, 1));
        rm1 = fmaxf(rm1, __shfl_xor_sync(0xffffffffu, rm1, 2));

        const float mn0 = fmaxf(m_run[0], rm0);
        const float mn1 = fmaxf(m_run[1], rm1);
        const float sc0 = __expf(m_run[0] - mn0);
        const float sc1 = __expf(m_run[1] - mn1);
        float rs0 = 0.0f, rs1 = 0.0f;
#pragma unroll
        for (int j = 0; j < 8; j++) {
            s[j][0] = __expf(s[j][0] - mn0); rs0 += s[j][0];
            s[j][1] = __expf(s[j][1] - mn0); rs0 += s[j][1];
            s[j][2] = __expf(s[j][2] - mn1); rs1 += s[j][2];
            s[j][3] = __expf(s[j][3] - mn1); rs1 += s[j][3];
        }
        rs0 += __shfl_xor_sync(0xffffffffu, rs0, 1);
        rs0 += __shfl_xor_sync(0xffffffffu, rs0, 2);
        rs1 += __shfl_xor_sync(0xffffffffu, rs1, 1);
        rs1 += __shfl_xor_sync(0xffffffffu, rs1, 2);
        l_run[0] = l_run[0] * sc0 + rs0;
        l_run[1] = l_run[1] * sc1 + rs1;
        m_run[0] = mn0;
        m_run[1] = mn1;
#pragma unroll
        for (int j = 0; j < 8; j++) {
            o[j][0] *= sc0; o[j][1] *= sc0;
            o[j][2] *= sc1; o[j][3] *= sc1;
        }

        // write P (warp-private rows) as halfs, consume via ldmatrix
#pragma unroll
        for (int j = 0; j < 8; j++) {
            *(uint32_t*)&Ps[ mrow      * APH + j * 8 + 2 * t] = f2h2(s[j][0], s[j][1]);
            *(uint32_t*)&Ps[(mrow + 8) * APH + j * 8 + 2 * t] = f2h2(s[j][2], s[j][3]);
        }
        __syncwarp();

        // O += P V
#pragma unroll
        for (int ks = 0; ks < 4; ks++) {
            const int kb = ks * 32;
            uint32_t ap[4];
            ldsm4(ap, sbP + preA + kb);
#pragma unroll
            for (int j2 = 0; j2 < 4; j2++) {
                uint32_t bf4[4];
                ldsm4(bf4, sbV + preB[j2] + kb);
                mma_f16(o[2 * j2],     ap, &bf4[0]);
                mma_f16(o[2 * j2 + 1], ap, &bf4[2]);
            }
        }
        __syncwarp();
    }

    // write output
    const float inv0 = 1.0f / l_run[0];
    const float inv1 = 1.0f / l_run[1];
    float* orow0 = xout + ((size_t)b * NQ + q0 + mrow    ) * D_MODEL + hh * HDIM;
    float* orow1 = xout + ((size_t)b * NQ + q0 + mrow + 8) * D_MODEL + hh * HDIM;
#pragma unroll
    for (int j = 0; j < 8; j++) {
        float2 v0, v1;
        v0.x = o[j][0] * inv0; v0.y = o[j][1] * inv0;
        v1.x = o[j][2] * inv1; v1.y = o[j][3] * inv1;
        *(float2*)(orow0 + j * 8 + 2 * t) = v0;
        *(float2*)(orow1 + j * 8 + 2 * t) = v1;
    }
}

// ---------------- launch ----------------
extern "C" void kernel_launch(void* const* d_in, const int* in_sizes, int n_in,
                              void* d_out, int out_size) {
    const float* q     = (const float*)d_in[0];
    const float* kv    = (const float*)d_in[1];
    const void*  mask  = d_in[2];
    const float* Wq    = (const float*)d_in[3];
    const float* Wkv   = (const float*)d_in[4];
    const float* Wproj = (const float*)d_in[5];
    const float* bproj = (const float*)d_in[6];
    float* out = (float*)d_out;

    float *qp, *kmat, *vmat, *xbuf;
    cudaGetSymbolAddress((void**)&qp,   g_qp);
    cudaGetSymbolAddress((void**)&kmat, g_k);
    cudaGetSymbolAddress((void**)&vmat, g_v);
    cudaGetSymbolAddress((void**)&xbuf, g_x);

    cudaFuncSetAttribute(attn_mma,
                         cudaFuncAttributeMaxDynamicSharedMemorySize, ATT_SMEM);

    detect_mask_kernel<<<1, 256>>>((const unsigned int*)mask);

    // qp = 0.125 * (q @ Wq)
    sgemm_mma<<<dim3(D_MODEL / 128, (BATCH * NQ) / 128), 256>>>(
        q, Wq, qp, nullptr, BATCH * NQ, D_MODEL, D_MODEL, 0.125f, nullptr, 0);

    // kvp = kv @ Wkv, split into k / v
    sgemm_mma<<<dim3((2 * D_MODEL) / 128, (BATCH * NKV) / 128), 256>>>(
        kv, Wkv, kmat, vmat, BATCH * NKV, 2 * D_MODEL, D_MODEL, 1.0f, nullptr,
        D_MODEL);

    // attention (fp16 tensor cores + ldmatrix)
    attn_mma<<<dim3(NQ / 64, NHEADS, BATCH), 128, ATT_SMEM>>>(
        qp, kmat, vmat, mask, xbuf);

    // out = x @ Wproj + bproj
    sgemm_mma<<<dim3(D_MODEL / 128, (BATCH * NQ) / 128), 256>>>(
        xbuf, Wproj, out, nullptr, BATCH * NQ, D_MODEL, D_MODEL, 1.0f, bproj, 0);
}

// round 7
// speedup vs baseline: 1.5539x; 1.5539x over previous
#include <cuda_runtime.h>
#include <cuda_fp16.h>
#include <cstdint>

#define D_MODEL 1024
#define NQ      1024
#define NKV     4096
#define BATCH   4
#define NHEADS  16
#define HDIM    64

// ---------------- scratch (device globals: allocation-free) ----------------
__device__ float g_qp[(size_t)BATCH * NQ  * D_MODEL];   // 16 MB
__device__ float g_k [(size_t)BATCH * NKV * D_MODEL];   // 64 MB
__device__ float g_v [(size_t)BATCH * NKV * D_MODEL];   // 64 MB
__device__ float g_x [(size_t)BATCH * NQ  * D_MODEL];   // 16 MB
__device__ int   g_mask_is_i32;

// ---------------- helpers ----------------
__device__ __forceinline__ uint32_t f2h2(float lo, float hi) {
    __half2 h = __floats2half2_rn(lo, hi);
    return *(uint32_t*)&h;
}
__device__ __forceinline__ void mma_f16(float* c, const uint32_t* a,
                                        const uint32_t* b) {
    asm volatile(
        "mma.sync.aligned.m16n8k16.row.col.f32.f16.f16.f32 "
        "{%0,%1,%2,%3}, {%4,%5,%6,%7}, {%8,%9}, {%0,%1,%2,%3};"
        : "+f"(c[0]), "+f"(c[1]), "+f"(c[2]), "+f"(c[3])
        : "r"(a[0]), "r"(a[1]), "r"(a[2]), "r"(a[3]), "r"(b[0]), "r"(b[1]));
}
__device__ __forceinline__ uint32_t smem_u32(const void* p) {
    uint32_t a;
    asm("{ .reg .u64 t; cvta.to.shared.u64 t, %1; cvt.u32.u64 %0, t; }"
        : "=r"(a) : "l"(p));
    return a;
}
__device__ __forceinline__ void ldsm4(uint32_t* d, uint32_t addr) {
    asm volatile(
        "ldmatrix.sync.aligned.m8n8.x4.shared.b16 {%0,%1,%2,%3}, [%4];"
        : "=r"(d[0]), "=r"(d[1]), "=r"(d[2]), "=r"(d[3]) : "r"(addr));
}

// ---------------- mask dtype detector ----------------
__global__ void detect_mask_kernel(const unsigned int* __restrict__ w) {
    __shared__ int bad;
    if (threadIdx.x == 0) bad = 0;
    __syncthreads();
    for (int i = threadIdx.x; i < 4096; i += 256)
        if (w[i] > 1u) bad = 1;
    __syncthreads();
    if (threadIdx.x == 0) g_mask_is_i32 = !bad;
}

// ---------------- fp16 mma.sync GEMM: 128x128 tile, K-chunk 32 -------------
// A [m][k] halfs; B stored N-major [n][k] halfs. All frags via ldmatrix.
#define LDH 40

__global__ __launch_bounds__(256, 2) void sgemm_mma(
    const float* __restrict__ A, const float* __restrict__ B,
    float* __restrict__ C0, float* __restrict__ C1,
    int M, int N, int K, float alpha, const float* __restrict__ bias, int splitN)
{
    __shared__ __align__(16) __half As[128][LDH];
    __shared__ __align__(16) __half Bsn[128][LDH];

    const int tid = threadIdx.x;
    const int w   = tid >> 5;
    const int lane = tid & 31;
    const int warpM = w >> 2;
    const int warpN = w & 3;
    const int bm = blockIdx.y * 128;
    const int bn = blockIdx.x * 128;

    const int r8 = tid >> 3;
    const int f8 = tid & 7;

    const uint32_t sbA = smem_u32(As);
    const uint32_t sbB = smem_u32(Bsn);

    const int lr   = lane & 7;
    const int lhi8 = ((lane >> 4) & 1) * 8;
    const int lhf  = (lane >> 3) & 1;
    uint32_t aoff[4], boff[2];
#pragma unroll
    for (int mt = 0; mt < 4; mt++)
        aoff[mt] = sbA + ((warpM * 64 + mt * 16 + (lane & 15)) * LDH +
                          (lane >> 4) * 8) * 2;
#pragma unroll
    for (int nt2 = 0; nt2 < 2; nt2++)
        boff[nt2] = sbB + ((warpN * 32 + nt2 * 16 + lhi8 + lr) * LDH +
                           lhf * 8) * 2;

    float acc[4][4][4];
#pragma unroll
    for (int mt = 0; mt < 4; mt++)
#pragma unroll
        for (int nt = 0; nt < 4; nt++)
#pragma unroll
            for (int i = 0; i < 4; i++) acc[mt][nt][i] = 0.0f;

    const int bn_n = tid & 127;
    const int kq_b = tid >> 7;

    for (int k0 = 0; k0 < K; k0 += 32) {
        float4 av[4];
#pragma unroll
        for (int p = 0; p < 4; p++)
            av[p] = *(const float4*)(A + (size_t)(bm + p * 32 + r8) * K + k0 + f8 * 4);
        float bld[4][4];
#pragma unroll
        for (int it = 0; it < 4; it++) {
            const int kk = (2 * it + kq_b) * 4;
            const float* Bp = B + (size_t)(k0 + kk) * N + bn + bn_n;
#pragma unroll
            for (int c = 0; c < 4; c++)
                bld[it][c] = Bp[(size_t)c * N];
        }

        __syncthreads();
#pragma unroll
        for (int p = 0; p < 4; p++) {
            uint2 hv;
            hv.x = f2h2(av[p].x, av[p].y);
            hv.y = f2h2(av[p].z, av[p].w);
            *(uint2*)&As[p * 32 + r8][f8 * 4] = hv;
        }
#pragma unroll
        for (int it = 0; it < 4; it++) {
            const int kk = (2 * it + kq_b) * 4;
            uint2 hv;
            hv.x = f2h2(bld[it][0], bld[it][1]);
            hv.y = f2h2(bld[it][2], bld[it][3]);
            *(uint2*)&Bsn[bn_n][kk] = hv;
        }
        __syncthreads();

#pragma unroll
        for (int ks = 0; ks < 2; ks++) {
            const int kb = ks * 32;   // 16 halfs in bytes
            uint32_t af[4][4];
#pragma unroll
            for (int mt = 0; mt < 4; mt++)
                ldsm4(af[mt], aoff[mt] + kb);
#pragma unroll
            for (int nt2 = 0; nt2 < 2; nt2++) {
                uint32_t bf4[4];
                ldsm4(bf4, boff[nt2] + kb);
#pragma unroll
                for (int mt = 0; mt < 4; mt++) {
                    mma_f16(acc[mt][2 * nt2],     af[mt], &bf4[0]);
                    mma_f16(acc[mt][2 * nt2 + 1], af[mt], &bf4[2]);
                }
            }
        }
    }

    const int g = lane >> 2;
    const int t = lane & 3;
#pragma unroll
    for (int mt = 0; mt < 4; mt++) {
#pragma unroll
        for (int nt = 0; nt < 4; nt++) {
            const int row0 = bm + warpM * 64 + mt * 16 + g;
            const int col  = bn + warpN * 32 + nt * 8 + 2 * t;
            float2 v0, v1;
            v0.x = alpha * acc[mt][nt][0];
            v0.y = alpha * acc[mt][nt][1];
            v1.x = alpha * acc[mt][nt][2];
            v1.y = alpha * acc[mt][nt][3];
            if (bias) {
                const float bx = bias[col], by = bias[col + 1];
                v0.x += bx; v0.y += by;
                v1.x += bx; v1.y += by;
            }
            float* dst;
            int ld;
            int c = col;
            if (splitN && col >= splitN) {
                ld = N - splitN; c = col - splitN; dst = C1;
            } else {
                ld = splitN ? splitN : N; dst = C0;
            }
            *(float2*)(dst + (size_t)row0 * ld + c)       = v0;
            *(float2*)(dst + (size_t)(row0 + 8) * ld + c) = v1;
        }
    }
}

// ---------------- flash attention: fp16 mma + ldmatrix ---------------------
// CTA: 64 q-rows x head x batch; 4 warps x 16 q-rows. KV tile 64.
#define APH 72
#define ATT_SMEM (3 * 64 * APH * 2 + 64 * 4)

__global__ __launch_bounds__(128, 3) void attn_mma(
    const float* __restrict__ qp, const float* __restrict__ kmat,
    const float* __restrict__ vmat, const void* __restrict__ maskp,
    float* __restrict__ xout)
{
    extern __shared__ char smc[];
    __half* Kn = (__half*)smc;            // [kv=64][APH] native (d contiguous)
    __half* Vt = Kn + 64 * APH;           // [d=64][APH] transposed (kv contig)
    __half* Ps = Vt + 64 * APH;           // Q staging, then P [q=64][APH]
    float* mskb = (float*)(Ps + 64 * APH);

    const int tid = threadIdx.x;
    const int w = tid >> 5, lane = tid & 31;
    const int g = lane >> 2, t = lane & 3;
    const int q0 = blockIdx.x * 64;
    const int hh = blockIdx.y;
    const int b  = blockIdx.z;

    const uint32_t sbK = smem_u32(Kn);
    const uint32_t sbV = smem_u32(Vt);
    const uint32_t sbP = smem_u32(Ps);

    const float* qbase = qp   + ((size_t)b * NQ + q0) * D_MODEL + hh * HDIM;
    const float* kbase = kmat + (size_t)b * NKV * D_MODEL + hh * HDIM;
    const float* vbase = vmat + (size_t)b * NKV * D_MODEL + hh * HDIM;
    const int mi32 = g_mask_is_i32;
    const unsigned char* m8  = (const unsigned char*)maskp + (size_t)b * NKV;
    const int*           m32 = (const int*)maskp           + (size_t)b * NKV;

    const int lr   = lane & 7;
    const int lhi8 = ((lane >> 4) & 1) * 8;
    const int lhf  = (lane >> 3) & 1;
    uint32_t preB[4];
#pragma unroll
    for (int j2 = 0; j2 < 4; j2++)
        preB[j2] = ((j2 * 16 + lhi8 + lr) * APH + lhf * 8) * 2;
    const uint32_t preA = ((w * 16 + (lane & 15)) * APH + (lane >> 4) * 8) * 2;

    // stage Q tile (warp-private rows)
    {
        const int r = tid >> 1, c0 = (tid & 1) * 32;
        const float* src = qbase + (size_t)r * D_MODEL + c0;
        __half* dst = &Ps[r * APH + c0];
#pragma unroll
        for (int i = 0; i < 4; i++) {
            float4 v0 = *(const float4*)(src + 8 * i);
            float4 v1 = *(const float4*)(src + 8 * i + 4);
            uint4 hv;
            hv.x = f2h2(v0.x, v0.y); hv.y = f2h2(v0.z, v0.w);
            hv.z = f2h2(v1.x, v1.y); hv.w = f2h2(v1.z, v1.w);
            *(uint4*)(dst + 8 * i) = hv;
        }
    }
    __syncthreads();

    // preload Q fragments (4 k16-steps over d=64)
    const int mrow = w * 16 + g;
    uint32_t aq[4][4];
#pragma unroll
    for (int ks = 0; ks < 4; ks++)
        ldsm4(aq[ks], sbP + preA + ks * 32);

    float m_run[2] = {-1e30f, -1e30f};
    float l_run[2] = {0.0f, 0.0f};
    float o[8][4];
#pragma unroll
    for (int j = 0; j < 8; j++)
#pragma unroll
        for (int i = 0; i < 4; i++) o[j][i] = 0.0f;

    for (int k0 = 0; k0 < NKV; k0 += 64) {
        __syncthreads();  // prior tile fully consumed

        // K tile native [kv][d] (vectorized half stores)
        {
            const int r = tid >> 1, c0 = (tid & 1) * 32;
            const float* src = kbase + (size_t)(k0 + r) * D_MODEL + c0;
            __half* dst = &Kn[r * APH + c0];
#pragma unroll
            for (int i = 0; i < 4; i++) {
                float4 v0 = *(const float4*)(src + 8 * i);
                float4 v1 = *(const float4*)(src + 8 * i + 4);
                uint4 hv;
                hv.x = f2h2(v0.x, v0.y); hv.y = f2h2(v0.z, v0.w);
                hv.z = f2h2(v1.x, v1.y); hv.w = f2h2(v1.z, v1.w);
                *(uint4*)(dst + 8 * i) = hv;
            }
        }
        // V tile transposed [d][kv]: thread handles a kv pair, 16 d values
        {
            const int kp = (tid & 31) * 2;
            const int c0 = (tid >> 5) * 16;
            const float* s0 = vbase + (size_t)(k0 + kp) * D_MODEL + c0;
            const float* s1 = s0 + D_MODEL;
#pragma unroll
            for (int i = 0; i < 4; i++) {
                float4 a = *(const float4*)(s0 + 4 * i);
                float4 c = *(const float4*)(s1 + 4 * i);
                const int d0 = c0 + 4 * i;
                *(uint32_t*)&Vt[(d0 + 0) * APH + kp] = f2h2(a.x, c.x);
                *(uint32_t*)&Vt[(d0 + 1) * APH + kp] = f2h2(a.y, c.y);
                *(uint32_t*)&Vt[(d0 + 2) * APH + kp] = f2h2(a.z, c.z);
                *(uint32_t*)&Vt[(d0 + 3) * APH + kp] = f2h2(a.w, c.w);
            }
        }
        // mask bias
        if (tid < 64) {
            const int kk = k0 + tid;
            const bool masked = mi32 ? (m32[kk] != 0) : (m8[kk] != 0);
            mskb[tid] = masked ? -1e30f : 0.0f;
        }
        __syncthreads();

        // S = Q K^T
        float s[8][4];
#pragma unroll
        for (int j = 0; j < 8; j++)
#pragma unroll
            for (int i = 0; i < 4; i++) s[j][i] = 0.0f;

#pragma unroll
        for (int ks = 0; ks < 4; ks++) {
            const int kb = ks * 32;
#pragma unroll
            for (int j2 = 0; j2 < 4; j2++) {
                uint32_t bf4[4];
                ldsm4(bf4, sbK + preB[j2] + kb);
                mma_f16(s[2 * j2],     aq[ks], &bf4[0]);
                mma_f16(s[2 * j2 + 1], aq[ks], &bf4[2]);
            }
        }

        // mask bias + online softmax (rows g and g+8)
        float rm0 = -1e30f, rm1 = -1e30f;
#pragma unroll
        for (int j = 0; j < 8; j++) {
            const float b0 = mskb[j * 8 + 2 * t];
            const float b1 = mskb[j * 8 + 2 * t + 1];
            s[j][0] += b0; s[j][1] += b1;
            s[j][2] += b0; s[j][3] += b1;
            rm0 = fmaxf(rm0, fmaxf(s[j][0], s[j][1]));
            rm1 = fmaxf(rm1, fmaxf(s[j][2], s[j][3]));
        }
        rm0 = fmaxf(rm0, __shfl_xor_sync(0xffffffffu, rm0, 1));
        rm0 = fmaxf(rm0, __shfl_xor_sync(0xffffffffu, rm0, 2));
        rm1 = fmaxf(rm1, __shfl_xor_sync(0xffffffffu, rm1, 1));
        rm1 = fmaxf(rm1, __shfl_xor_sync(0xffffffffu, rm1, 2));

        const float mn0 = fmaxf(m_run[0], rm0);
        const float mn1 = fmaxf(m_run[1], rm1);
        const float sc0 = __expf(m_run[0] - mn0);
        const float sc1 = __expf(m_run[1] - mn1);
        float rs0 = 0.0f, rs1 = 0.0f;
#pragma unroll
        for (int j = 0; j < 8; j++) {
            s[j][0] = __expf(s[j][0] - mn0); rs0 += s[j][0];
            s[j][1] = __expf(s[j][1] - mn0); rs0 += s[j][1];
            s[j][2] = __expf(s[j][2] - mn1); rs1 += s[j][2];
            s[j][3] = __expf(s[j][3] - mn1); rs1 += s[j][3];
        }
        rs0 += __shfl_xor_sync(0xffffffffu, rs0, 1);
        rs0 += __shfl_xor_sync(0xffffffffu, rs0, 2);
        rs1 += __shfl_xor_sync(0xffffffffu, rs1, 1);
        rs1 += __shfl_xor_sync(0xffffffffu, rs1, 2);
        l_run[0] = l_run[0] * sc0 + rs0;
        l_run[1] = l_run[1] * sc1 + rs1;
        m_run[0] = mn0;
        m_run[1] = mn1;
#pragma unroll
        for (int j = 0; j < 8; j++) {
            o[j][0] *= sc0; o[j][1] *= sc0;
            o[j][2] *= sc1; o[j][3] *= sc1;
        }

        // write P (warp-private rows) as halfs, consume via ldmatrix
#pragma unroll
        for (int j = 0; j < 8; j++) {
            *(uint32_t*)&Ps[ mrow      * APH + j * 8 + 2 * t] = f2h2(s[j][0], s[j][1]);
            *(uint32_t*)&Ps[(mrow + 8) * APH + j * 8 + 2 * t] = f2h2(s[j][2], s[j][3]);
        }
        __syncwarp();

        // O += P V
#pragma unroll
        for (int ks = 0; ks < 4; ks++) {
            const int kb = ks * 32;
            uint32_t ap[4];
            ldsm4(ap, sbP + preA + kb);
#pragma unroll
            for (int j2 = 0; j2 < 4; j2++) {
                uint32_t bf4[4];
                ldsm4(bf4, sbV + preB[j2] + kb);
                mma_f16(o[2 * j2],     ap, &bf4[0]);
                mma_f16(o[2 * j2 + 1], ap, &bf4[2]);
            }
        }
        __syncwarp();
    }

    // write output
    const float inv0 = 1.0f / l_run[0];
    const float inv1 = 1.0f / l_run[1];
    float* orow0 = xout + ((size_t)b * NQ + q0 + mrow    ) * D_MODEL + hh * HDIM;
    float* orow1 = xout + ((size_t)b * NQ + q0 + mrow + 8) * D_MODEL + hh * HDIM;
#pragma unroll
    for (int j = 0; j < 8; j++) {
        float2 v0, v1;
        v0.x = o[j][0] * inv0; v0.y = o[j][1] * inv0;
        v1.x = o[j][2] * inv1; v1.y = o[j][3] * inv1;
        *(float2*)(orow0 + j * 8 + 2 * t) = v0;
        *(float2*)(orow1 + j * 8 + 2 * t) = v1;
    }
}

// ---------------- launch ----------------
extern "C" void kernel_launch(void* const* d_in, const int* in_sizes, int n_in,
                              void* d_out, int out_size) {
    const float* q     = (const float*)d_in[0];
    const float* kv    = (const float*)d_in[1];
    const void*  mask  = d_in[2];
    const float* Wq    = (const float*)d_in[3];
    const float* Wkv   = (const float*)d_in[4];
    const float* Wproj = (const float*)d_in[5];
    const float* bproj = (const float*)d_in[6];
    float* out = (float*)d_out;

    float *qp, *kmat, *vmat, *xbuf;
    cudaGetSymbolAddress((void**)&qp,   g_qp);
    cudaGetSymbolAddress((void**)&kmat, g_k);
    cudaGetSymbolAddress((void**)&vmat, g_v);
    cudaGetSymbolAddress((void**)&xbuf, g_x);

    cudaFuncSetAttribute(attn_mma,
                         cudaFuncAttributeMaxDynamicSharedMemorySize, ATT_SMEM);

    detect_mask_kernel<<<1, 256>>>((const unsigned int*)mask);

    // qp = 0.125 * (q @ Wq)
    sgemm_mma<<<dim3(D_MODEL / 128, (BATCH * NQ) / 128), 256>>>(
        q, Wq, qp, nullptr, BATCH * NQ, D_MODEL, D_MODEL, 0.125f, nullptr, 0);

    // kvp = kv @ Wkv, split into k / v
    sgemm_mma<<<dim3((2 * D_MODEL) / 128, (BATCH * NKV) / 128), 256>>>(
        kv, Wkv, kmat, vmat, BATCH * NKV, 2 * D_MODEL, D_MODEL, 1.0f, nullptr,
        D_MODEL);

    // attention (fp16 tensor cores + ldmatrix)
    attn_mma<<<dim3(NQ / 64, NHEADS, BATCH), 128, ATT_SMEM>>>(
        qp, kmat, vmat, mask, xbuf);

    // out = x @ Wproj + bproj
    sgemm_mma<<<dim3(D_MODEL / 128, (BATCH * NQ) / 128), 256>>>(
        xbuf, Wproj, out, nullptr, BATCH * NQ, D_MODEL, D_MODEL, 1.0f, bproj, 0);
}

// round 8
// speedup vs baseline: 2.7469x; 1.7678x over previous
#include <cuda_runtime.h>
#include <cuda_fp16.h>
#include <cstdint>

#define D_MODEL 1024
#define NQ      1024
#define NKV     4096
#define BATCH   4
#define NHEADS  16
#define HDIM    64

// ---------------- scratch (device globals: allocation-free) ----------------
__device__ __align__(16) __half g_qp [(size_t)BATCH * NQ  * D_MODEL];  // 8 MB
__device__ __align__(16) __half g_kh [(size_t)BATCH * NKV * D_MODEL];  // 32 MB
__device__ __align__(16) __half g_vT [(size_t)BATCH * NKV * D_MODEL];  // 32 MB [b][h][d][kv]
__device__ __align__(16) float  g_x  [(size_t)BATCH * NQ  * D_MODEL];  // 16 MB
__device__ __align__(16) float  g_mb [(size_t)BATCH * NKV];            // mask bias
__device__ int g_mask_is_i32;

// ---------------- helpers ----------------
__device__ __forceinline__ uint32_t f2h2(float lo, float hi) {
    __half2 h = __floats2half2_rn(lo, hi);
    return *(uint32_t*)&h;
}
__device__ __forceinline__ void mma_f16(float* c, const uint32_t* a,
                                        const uint32_t* b) {
    asm volatile(
        "mma.sync.aligned.m16n8k16.row.col.f32.f16.f16.f32 "
        "{%0,%1,%2,%3}, {%4,%5,%6,%7}, {%8,%9}, {%0,%1,%2,%3};"
        : "+f"(c[0]), "+f"(c[1]), "+f"(c[2]), "+f"(c[3])
        : "r"(a[0]), "r"(a[1]), "r"(a[2]), "r"(a[3]), "r"(b[0]), "r"(b[1]));
}
__device__ __forceinline__ uint32_t smem_u32(const void* p) {
    uint32_t a;
    asm("{ .reg .u64 t; cvta.to.shared.u64 t, %1; cvt.u32.u64 %0, t; }"
        : "=r"(a) : "l"(p));
    return a;
}
__device__ __forceinline__ void ldsm4(uint32_t* d, uint32_t addr) {
    asm volatile(
        "ldmatrix.sync.aligned.m8n8.x4.shared.b16 {%0,%1,%2,%3}, [%4];"
        : "=r"(d[0]), "=r"(d[1]), "=r"(d[2]), "=r"(d[3]) : "r"(addr));
}
__device__ __forceinline__ void cpa16(uint32_t smem, const void* g) {
    asm volatile("cp.async.cg.shared.global [%0], [%1], 16;"
                 :: "r"(smem), "l"(g) : "memory");
}
#define CP_COMMIT() asm volatile("cp.async.commit_group;" ::: "memory")

// ---------------- mask dtype detector + bias builder ----------------
__global__ void detect_mask_kernel(const unsigned int* __restrict__ w) {
    __shared__ int bad;
    if (threadIdx.x == 0) bad = 0;
    __syncthreads();
    for (int i = threadIdx.x; i < 4096; i += 256)
        if (w[i] > 1u) bad = 1;
    __syncthreads();
    if (threadIdx.x == 0) g_mask_is_i32 = !bad;
}
__global__ void maskbias_kernel(const void* __restrict__ maskp) {
    const int i = blockIdx.x * 256 + threadIdx.x;   // BATCH*NKV = 16384
    const bool m = g_mask_is_i32 ? (((const int*)maskp)[i] != 0)
                                 : (((const unsigned char*)maskp)[i] != 0);
    g_mb[i] = m ? -1e30f : 0.0f;
}

// ---------------- fp16 mma.sync GEMM: 128x128 tile, K-chunk 32 -------------
// ohalf: C outputs are __half (alpha applied, no bias).
// vtrans: cols >= splitN go to C1 as transposed V [b][h][d][kv].
#define LDH 40

__global__ __launch_bounds__(256, 2) void sgemm_mma(
    const float* __restrict__ A, const float* __restrict__ B,
    void* __restrict__ C0, void* __restrict__ C1,
    int M, int N, int K, float alpha, const float* __restrict__ bias,
    int splitN, int ohalf, int vtrans)
{
    __shared__ __align__(16) __half As[128][LDH];
    __shared__ __align__(16) __half Bsn[128][LDH];

    const int tid = threadIdx.x;
    const int w   = tid >> 5;
    const int lane = tid & 31;
    const int warpM = w >> 2;
    const int warpN = w & 3;
    const int bm = blockIdx.y * 128;
    const int bn = blockIdx.x * 128;

    const int r8 = tid >> 3;
    const int f8 = tid & 7;

    const uint32_t sbA = smem_u32(As);
    const uint32_t sbB = smem_u32(Bsn);

    const int lr   = lane & 7;
    const int lhi8 = ((lane >> 4) & 1) * 8;
    const int lhf  = (lane >> 3) & 1;
    uint32_t aoff[4], boff[2];
#pragma unroll
    for (int mt = 0; mt < 4; mt++)
        aoff[mt] = sbA + ((warpM * 64 + mt * 16 + (lane & 15)) * LDH +
                          (lane >> 4) * 8) * 2;
#pragma unroll
    for (int nt2 = 0; nt2 < 2; nt2++)
        boff[nt2] = sbB + ((warpN * 32 + nt2 * 16 + lhi8 + lr) * LDH +
                           lhf * 8) * 2;

    float acc[4][4][4];
#pragma unroll
    for (int mt = 0; mt < 4; mt++)
#pragma unroll
        for (int nt = 0; nt < 4; nt++)
#pragma unroll
            for (int i = 0; i < 4; i++) acc[mt][nt][i] = 0.0f;

    const int bn_n = tid & 127;
    const int kq_b = tid >> 7;

    for (int k0 = 0; k0 < K; k0 += 32) {
        float4 av[4];
#pragma unroll
        for (int p = 0; p < 4; p++)
            av[p] = *(const float4*)(A + (size_t)(bm + p * 32 + r8) * K + k0 + f8 * 4);
        float bld[4][4];
#pragma unroll
        for (int it = 0; it < 4; it++) {
            const int kk = (2 * it + kq_b) * 4;
            const float* Bp = B + (size_t)(k0 + kk) * N + bn + bn_n;
#pragma unroll
            for (int c = 0; c < 4; c++)
                bld[it][c] = Bp[(size_t)c * N];
        }

        __syncthreads();
#pragma unroll
        for (int p = 0; p < 4; p++) {
            uint2 hv;
            hv.x = f2h2(av[p].x, av[p].y);
            hv.y = f2h2(av[p].z, av[p].w);
            *(uint2*)&As[p * 32 + r8][f8 * 4] = hv;
        }
#pragma unroll
        for (int it = 0; it < 4; it++) {
            const int kk = (2 * it + kq_b) * 4;
            uint2 hv;
            hv.x = f2h2(bld[it][0], bld[it][1]);
            hv.y = f2h2(bld[it][2], bld[it][3]);
            *(uint2*)&Bsn[bn_n][kk] = hv;
        }
        __syncthreads();

#pragma unroll
        for (int ks = 0; ks < 2; ks++) {
            const int kb = ks * 32;
            uint32_t af[4][4];
#pragma unroll
            for (int mt = 0; mt < 4; mt++)
                ldsm4(af[mt], aoff[mt] + kb);
#pragma unroll
            for (int nt2 = 0; nt2 < 2; nt2++) {
                uint32_t bf4[4];
                ldsm4(bf4, boff[nt2] + kb);
#pragma unroll
                for (int mt = 0; mt < 4; mt++) {
                    mma_f16(acc[mt][2 * nt2],     af[mt], &bf4[0]);
                    mma_f16(acc[mt][2 * nt2 + 1], af[mt], &bf4[2]);
                }
            }
        }
    }

    const int g = lane >> 2;
    const int t = lane & 3;
#pragma unroll
    for (int mt = 0; mt < 4; mt++) {
#pragma unroll
        for (int nt = 0; nt < 4; nt++) {
            const int row0 = bm + warpM * 64 + mt * 16 + g;
            const int col  = bn + warpN * 32 + nt * 8 + 2 * t;
            float c0 = alpha * acc[mt][nt][0];
            float c1 = alpha * acc[mt][nt][1];
            float c2 = alpha * acc[mt][nt][2];
            float c3 = alpha * acc[mt][nt][3];
            if (ohalf) {
                if (vtrans && col >= splitN) {
                    const int cc = col - splitN;
                    const int hidx = cc >> 6, d = cc & 63;
                    const int bb = row0 >> 12, kv = row0 & (NKV - 1);
                    __half* base = (__half*)C1 +
                        (((size_t)bb * NHEADS + hidx) * HDIM + d) * NKV + kv;
                    base[0]       = __float2half_rn(c0);   // (d,   kv)
                    base[NKV]     = __float2half_rn(c1);   // (d+1, kv)
                    base[8]       = __float2half_rn(c2);   // (d,   kv+8)
                    base[NKV + 8] = __float2half_rn(c3);   // (d+1, kv+8)
                } else {
                    const int ld = splitN ? splitN : N;
                    __half* dst = (__half*)C0;
                    *(uint32_t*)(dst + (size_t)row0 * ld + col)       = f2h2(c0, c1);
                    *(uint32_t*)(dst + (size_t)(row0 + 8) * ld + col) = f2h2(c2, c3);
                }
            } else {
                if (bias) {
                    const float bx = bias[col], by = bias[col + 1];
                    c0 += bx; c1 += by; c2 += bx; c3 += by;
                }
                float* dst = (float*)C0;
                float2 v0 = {c0, c1}, v1 = {c2, c3};
                *(float2*)(dst + (size_t)row0 * N + col)       = v0;
                *(float2*)(dst + (size_t)(row0 + 8) * N + col) = v1;
            }
        }
    }
}

// ---------------- flash attention: fp16 mma + cp.async double buffer -------
// CTA: 64 q-rows x head x batch; 4 warps x 16 q-rows. KV tile 64.
// smem layout (bytes): K0 K1 V0 V1 (9216 each), P 9216, M0 M1 (256 each)
#define TILE_B 9216
#define ATT_SMEM (4 * TILE_B + TILE_B + 2 * 256)

__global__ __launch_bounds__(128, 3) void attn_mma(
    const __half* __restrict__ qp, const __half* __restrict__ kh,
    const __half* __restrict__ vth, const float* __restrict__ mb,
    float* __restrict__ xout)
{
    extern __shared__ char smc[];
    const uint32_t sb = smem_u32(smc);
    const uint32_t sK0 = sb, sV0 = sb + 2 * TILE_B;
    const uint32_t sP  = sb + 4 * TILE_B;
    const uint32_t sM0 = sb + 5 * TILE_B;
    __half* Psh = (__half*)(smc + 4 * TILE_B);

    const int tid = threadIdx.x;
    const int w = tid >> 5, lane = tid & 31;
    const int g = lane >> 2, t = lane & 3;
    const int q0 = blockIdx.x * 64;
    const int hh = blockIdx.y;
    const int b  = blockIdx.z;

    const __half* qbase  = qp  + ((size_t)b * NQ + q0) * D_MODEL + hh * HDIM;
    const __half* kbase  = kh  + (size_t)b * NKV * D_MODEL + hh * HDIM;
    const __half* vtbase = vth + ((size_t)b * NHEADS + hh) * HDIM * NKV;
    const float*  mbase  = mb  + (size_t)b * NKV;

    const int lr   = lane & 7;
    const int lhi8 = ((lane >> 4) & 1) * 8;
    const int lhf  = (lane >> 3) & 1;
    uint32_t preB[4];
#pragma unroll
    for (int j2 = 0; j2 < 4; j2++)
        preB[j2] = ((j2 * 16 + lhi8 + lr) * 72 + lhf * 8) * 2;
    const uint32_t preA = ((w * 16 + (lane & 15)) * 72 + (lane >> 4) * 8) * 2;

    // stage Q tile (warp-private rows, raw half copy)
    {
        const int r = tid >> 1, c0 = (tid & 1) * 32;
        const uint4* src = (const uint4*)(qbase + (size_t)r * D_MODEL + c0);
        uint4* dst = (uint4*)(Psh + r * 72 + c0);
#pragma unroll
        for (int i = 0; i < 4; i++) dst[i] = src[i];
    }
    __syncthreads();

    const int mrow = w * 16 + g;
    uint32_t aq[4][4];
#pragma unroll
    for (int ks = 0; ks < 4; ks++)
        ldsm4(aq[ks], sP + preA + ks * 32);

    float m_run[2] = {-1e30f, -1e30f};
    float l_run[2] = {0.0f, 0.0f};
    float o[8][4];
#pragma unroll
    for (int j = 0; j < 8; j++)
#pragma unroll
        for (int i = 0; i < 4; i++) o[j][i] = 0.0f;

    // prefetch: K rows [kv][d], V rows [d][kv], mask bias
#define PREFETCH(p, k0)                                                        \
    do {                                                                       \
        const uint32_t kb_ = sK0 + (p) * TILE_B;                               \
        const uint32_t vb_ = sV0 + (p) * TILE_B;                               \
        _Pragma("unroll")                                                      \
        for (int i_ = 0; i_ < 4; i_++) {                                       \
            const int c_ = tid + i_ * 128;                                     \
            const int r_ = c_ >> 3, o_ = (c_ & 7) * 8;                         \
            cpa16(kb_ + r_ * 144 + o_ * 2,                                     \
                  kbase + (size_t)((k0) + r_) * D_MODEL + o_);                 \
            cpa16(vb_ + r_ * 144 + o_ * 2,                                     \
                  vtbase + (size_t)r_ * NKV + (k0) + o_);                      \
        }                                                                      \
        if (tid < 16)                                                          \
            cpa16(sM0 + (p) * 256 + tid * 16, mbase + (k0) + tid * 4);         \
    } while (0)

    PREFETCH(0, 0);
    CP_COMMIT();

    for (int tile = 0; tile < NKV / 64; tile++) {
        const int p = tile & 1;
        __syncthreads();   // all threads done with buffer p^1 (tile-1 compute)
        if (tile + 1 < NKV / 64) {
            PREFETCH(p ^ 1, (tile + 1) * 64);
            CP_COMMIT();
            asm volatile("cp.async.wait_group 1;" ::: "memory");
        } else {
            asm volatile("cp.async.wait_group 0;" ::: "memory");
        }
        __syncthreads();

        const uint32_t kbuf = sK0 + p * TILE_B;
        const uint32_t vbuf = sV0 + p * TILE_B;
        const float* mskb = (const float*)(smc + 5 * TILE_B + p * 256);

        // S = Q K^T
        float s[8][4];
#pragma unroll
        for (int j = 0; j < 8; j++)
#pragma unroll
            for (int i = 0; i < 4; i++) s[j][i] = 0.0f;

#pragma unroll
        for (int ks = 0; ks < 4; ks++) {
            const int kb = ks * 32;
#pragma unroll
            for (int j2 = 0; j2 < 4; j2++) {
                uint32_t bf4[4];
                ldsm4(bf4, kbuf + preB[j2] + kb);
                mma_f16(s[2 * j2],     aq[ks], &bf4[0]);
                mma_f16(s[2 * j2 + 1], aq[ks], &bf4[2]);
            }
        }

        // mask bias + online softmax (rows g and g+8)
        float rm0 = -1e30f, rm1 = -1e30f;
#pragma unroll
        for (int j = 0; j < 8; j++) {
            const float b0 = mskb[j * 8 + 2 * t];
            const float b1 = mskb[j * 8 + 2 * t + 1];
            s[j][0] += b0; s[j][1] += b1;
            s[j][2] += b0; s[j][3] += b1;
            rm0 = fmaxf(rm0, fmaxf(s[j][0], s[j][1]));
            rm1 = fmaxf(rm1, fmaxf(s[j][2], s[j][3]));
        }
        rm0 = fmaxf(rm0, __shfl_xor_sync(0xffffffffu, rm0, 1));
        rm0 = fmaxf(rm0, __shfl_xor_sync(0xffffffffu, rm0, 2));
        rm1 = fmaxf(rm1, __shfl_xor_sync(0xffffffffu, rm1, 1));
        rm1 = fmaxf(rm1, __shfl_xor_sync(0xffffffffu, rm1, 2));

        const float mn0 = fmaxf(m_run[0], rm0);
        const float mn1 = fmaxf(m_run[1], rm1);
        const float sc0 = __expf(m_run[0] - mn0);
        const float sc1 = __expf(m_run[1] - mn1);
        float rs0 = 0.0f, rs1 = 0.0f;
#pragma unroll
        for (int j = 0; j < 8; j++) {
            s[j][0] = __expf(s[j][0] - mn0); rs0 += s[j][0];
            s[j][1] = __expf(s[j][1] - mn0); rs0 += s[j][1];
            s[j][2] = __expf(s[j][2] - mn1); rs1 += s[j][2];
            s[j][3] = __expf(s[j][3] - mn1); rs1 += s[j][3];
        }
        rs0 += __shfl_xor_sync(0xffffffffu, rs0, 1);
        rs0 += __shfl_xor_sync(0xffffffffu, rs0, 2);
        rs1 += __shfl_xor_sync(0xffffffffu, rs1, 1);
        rs1 += __shfl_xor_sync(0xffffffffu, rs1, 2);
        l_run[0] = l_run[0] * sc0 + rs0;
        l_run[1] = l_run[1] * sc1 + rs1;
        m_run[0] = mn0;
        m_run[1] = mn1;
#pragma unroll
        for (int j = 0; j < 8; j++) {
            o[j][0] *= sc0; o[j][1] *= sc0;
            o[j][2] *= sc1; o[j][3] *= sc1;
        }

        // write P (warp-private rows) as halfs, consume via ldmatrix
#pragma unroll
        for (int j = 0; j < 8; j++) {
            *(uint32_t*)&Psh[ mrow      * 72 + j * 8 + 2 * t] = f2h2(s[j][0], s[j][1]);
            *(uint32_t*)&Psh[(mrow + 8) * 72 + j * 8 + 2 * t] = f2h2(s[j][2], s[j][3]);
        }
        __syncwarp();

        // O += P V
#pragma unroll
        for (int ks = 0; ks < 4; ks++) {
            const int kb = ks * 32;
            uint32_t ap[4];
            ldsm4(ap, sP + preA + kb);
#pragma unroll
            for (int j2 = 0; j2 < 4; j2++) {
                uint32_t bf4[4];
                ldsm4(bf4, vbuf + preB[j2] + kb);
                mma_f16(o[2 * j2],     ap, &bf4[0]);
                mma_f16(o[2 * j2 + 1], ap, &bf4[2]);
            }
        }
        __syncwarp();
    }

    // write output
    const float inv0 = 1.0f / l_run[0];
    const float inv1 = 1.0f / l_run[1];
    float* orow0 = xout + ((size_t)b * NQ + q0 + mrow    ) * D_MODEL + hh * HDIM;
    float* orow1 = xout + ((size_t)b * NQ + q0 + mrow + 8) * D_MODEL + hh * HDIM;
#pragma unroll
    for (int j = 0; j < 8; j++) {
        float2 v0, v1;
        v0.x = o[j][0] * inv0; v0.y = o[j][1] * inv0;
        v1.x = o[j][2] * inv1; v1.y = o[j][3] * inv1;
        *(float2*)(orow0 + j * 8 + 2 * t) = v0;
        *(float2*)(orow1 + j * 8 + 2 * t) = v1;
    }
}

// ---------------- launch ----------------
extern "C" void kernel_launch(void* const* d_in, const int* in_sizes, int n_in,
                              void* d_out, int out_size) {
    const float* q     = (const float*)d_in[0];
    const float* kv    = (const float*)d_in[1];
    const void*  mask  = d_in[2];
    const float* Wq    = (const float*)d_in[3];
    const float* Wkv   = (const float*)d_in[4];
    const float* Wproj = (const float*)d_in[5];
    const float* bproj = (const float*)d_in[6];
    float* out = (float*)d_out;

    __half *qp, *kh, *vt;
    float *xbuf, *mb;
    cudaGetSymbolAddress((void**)&qp,   g_qp);
    cudaGetSymbolAddress((void**)&kh,   g_kh);
    cudaGetSymbolAddress((void**)&vt,   g_vT);
    cudaGetSymbolAddress((void**)&xbuf, g_x);
    cudaGetSymbolAddress((void**)&mb,   g_mb);

    cudaFuncSetAttribute(attn_mma,
                         cudaFuncAttributeMaxDynamicSharedMemorySize, ATT_SMEM);

    detect_mask_kernel<<<1, 256>>>((const unsigned int*)mask);
    maskbias_kernel<<<(BATCH * NKV) / 256, 256>>>(mask);

    // qp = 0.125 * (q @ Wq)  -> half
    sgemm_mma<<<dim3(D_MODEL / 128, (BATCH * NQ) / 128), 256>>>(
        q, Wq, qp, nullptr, BATCH * NQ, D_MODEL, D_MODEL, 0.125f, nullptr,
        0, 1, 0);

    // kvp = kv @ Wkv -> k half linear, v half transposed
    sgemm_mma<<<dim3((2 * D_MODEL) / 128, (BATCH * NKV) / 128), 256>>>(
        kv, Wkv, kh, vt, BATCH * NKV, 2 * D_MODEL, D_MODEL, 1.0f, nullptr,
        D_MODEL, 1, 1);

    // attention (fp16 tensor cores + cp.async pipeline)
    attn_mma<<<dim3(NQ / 64, NHEADS, BATCH), 128, ATT_SMEM>>>(
        qp, kh, vt, mb, xbuf);

    // out = x @ Wproj + bproj  (float)
    sgemm_mma<<<dim3(D_MODEL / 128, (BATCH * NQ) / 128), 256>>>(
        xbuf, Wproj, out, nullptr, BATCH * NQ, D_MODEL, D_MODEL, 1.0f, bproj,
        0, 0, 0);
}

// round 9
// speedup vs baseline: 2.7566x; 1.0036x over previous
#include <cuda_runtime.h>
#include <cuda_fp16.h>
#include <cstdint>

#define D_MODEL 1024
#define NQ      1024
#define NKV     4096
#define BATCH   4
#define NHEADS  16
#define HDIM    64

// ---------------- scratch (device globals: allocation-free) ----------------
__device__ __align__(16) __half g_qh  [(size_t)BATCH * NQ  * D_MODEL];  // q  f16
__device__ __align__(16) __half g_kvh [(size_t)BATCH * NKV * D_MODEL];  // kv f16
__device__ __align__(16) __half g_wqt [(size_t)D_MODEL * D_MODEL];      // Wq^T
__device__ __align__(16) __half g_wkvt[(size_t)2 * D_MODEL * D_MODEL];  // Wkv^T
__device__ __align__(16) __half g_wpt [(size_t)D_MODEL * D_MODEL];      // Wproj^T
__device__ __align__(16) __half g_qp  [(size_t)BATCH * NQ  * D_MODEL];  // q-proj
__device__ __align__(16) __half g_kh  [(size_t)BATCH * NKV * D_MODEL];  // k
__device__ __align__(16) __half g_vT  [(size_t)BATCH * NKV * D_MODEL];  // v [b][h][d][kv]
__device__ __align__(16) __half g_xh  [(size_t)BATCH * NQ  * D_MODEL];  // attn out
__device__ __align__(16) float  g_mb  [(size_t)BATCH * NKV];            // mask bias
__device__ int g_mask_is_i32;

// ---------------- helpers ----------------
__device__ __forceinline__ uint32_t f2h2(float lo, float hi) {
    __half2 h = __floats2half2_rn(lo, hi);
    return *(uint32_t*)&h;
}
__device__ __forceinline__ void mma_f16(float* c, const uint32_t* a,
                                        const uint32_t* b) {
    asm volatile(
        "mma.sync.aligned.m16n8k16.row.col.f32.f16.f16.f32 "
        "{%0,%1,%2,%3}, {%4,%5,%6,%7}, {%8,%9}, {%0,%1,%2,%3};"
        : "+f"(c[0]), "+f"(c[1]), "+f"(c[2]), "+f"(c[3])
        : "r"(a[0]), "r"(a[1]), "r"(a[2]), "r"(a[3]), "r"(b[0]), "r"(b[1]));
}
__device__ __forceinline__ uint32_t smem_u32(const void* p) {
    uint32_t a;
    asm("{ .reg .u64 t; cvta.to.shared.u64 t, %1; cvt.u32.u64 %0, t; }"
        : "=r"(a) : "l"(p));
    return a;
}
__device__ __forceinline__ void ldsm4(uint32_t* d, uint32_t addr) {
    asm volatile(
        "ldmatrix.sync.aligned.m8n8.x4.shared.b16 {%0,%1,%2,%3}, [%4];"
        : "=r"(d[0]), "=r"(d[1]), "=r"(d[2]), "=r"(d[3]) : "r"(addr));
}
__device__ __forceinline__ void cpa16(uint32_t smem, const void* g) {
    asm volatile("cp.async.cg.shared.global [%0], [%1], 16;"
                 :: "r"(smem), "l"(g) : "memory");
}
#define CP_COMMIT() asm volatile("cp.async.commit_group;" ::: "memory")
#define CP_WAIT(n)  asm volatile("cp.async.wait_group %0;" :: "n"(n) : "memory")

// ---------------- prep kernels ----------------
__global__ void detect_mask_kernel(const unsigned int* __restrict__ w) {
    __shared__ int bad;
    if (threadIdx.x == 0) bad = 0;
    __syncthreads();
    for (int i = threadIdx.x; i < 4096; i += 256)
        if (w[i] > 1u) bad = 1;
    __syncthreads();
    if (threadIdx.x == 0) g_mask_is_i32 = !bad;
}
__global__ void maskbias_kernel(const void* __restrict__ maskp) {
    const int i = blockIdx.x * 256 + threadIdx.x;
    const bool m = g_mask_is_i32 ? (((const int*)maskp)[i] != 0)
                                 : (((const unsigned char*)maskp)[i] != 0);
    g_mb[i] = m ? -1e30f : 0.0f;
}
// f32 -> f16 (n multiple of 2048)
__global__ void cvt_h_kernel(const float* __restrict__ src,
                             __half* __restrict__ dst) {
    const size_t i = ((size_t)blockIdx.x * 256 + threadIdx.x) * 8;
    float4 a = *(const float4*)(src + i);
    float4 b = *(const float4*)(src + i + 4);
    uint4 h;
    h.x = f2h2(a.x, a.y); h.y = f2h2(a.z, a.w);
    h.z = f2h2(b.x, b.y); h.w = f2h2(b.z, b.w);
    *(uint4*)(dst + i) = h;
}
// W [K][N] f32 -> Wt [N][K] f16  (tiles 32x32; block 32x8)
__global__ void transpose_h_kernel(const float* __restrict__ W,
                                   __half* __restrict__ Wt, int K, int N) {
    __shared__ float tile[32][33];
    const int n0 = blockIdx.x * 32, k0 = blockIdx.y * 32;
    const int tx = threadIdx.x, ty = threadIdx.y;
#pragma unroll
    for (int i = 0; i < 4; i++)
        tile[ty + i * 8][tx] = W[(size_t)(k0 + ty + i * 8) * N + n0 + tx];
    __syncthreads();
#pragma unroll
    for (int i = 0; i < 4; i++)
        Wt[(size_t)(n0 + ty + i * 8) * K + k0 + tx] =
            __float2half_rn(tile[tx][ty + i * 8]);
}

// ---------------- fp16 GEMM: cp.async double-buffered, K-chunk 64 ----------
// A [M][K] half; Bt [N][K] half. C: half (ohalf) or float (+bias).
// vtrans: cols >= splitN scattered to C1 as V^T [b][h][d][kv].
#define GLP 72                     // smem pitch in halves (144 B rows)
#define GBUF 18432                 // one 128x72 half buffer
#define HG_SMEM (4 * GBUF)         // A0 A1 B0 B1

__global__ __launch_bounds__(256, 2) void hgemm(
    const __half* __restrict__ A, const __half* __restrict__ Bt,
    void* __restrict__ C0, void* __restrict__ C1,
    int M, int N, int K, float alpha, const float* __restrict__ bias,
    int splitN, int ohalf, int vtrans)
{
    extern __shared__ char smc[];
    const uint32_t sbS = smem_u32(smc);

    const int tid = threadIdx.x;
    const int w   = tid >> 5;
    const int lane = tid & 31;
    const int warpM = w >> 2;
    const int warpN = w & 3;
    const int bm = blockIdx.y * 128;
    const int bn = blockIdx.x * 128;

    const int lr   = lane & 7;
    const int lhi8 = ((lane >> 4) & 1) * 8;
    const int lhf  = (lane >> 3) & 1;
    uint32_t aoff[4], boff[2];
#pragma unroll
    for (int mt = 0; mt < 4; mt++)
        aoff[mt] = sbS + ((warpM * 64 + mt * 16 + (lane & 15)) * GLP +
                          (lane >> 4) * 8) * 2;
#pragma unroll
    for (int nt2 = 0; nt2 < 2; nt2++)
        boff[nt2] = sbS + 2 * GBUF +
                    ((warpN * 32 + nt2 * 16 + lhi8 + lr) * GLP + lhf * 8) * 2;

    float acc[4][4][4];
#pragma unroll
    for (int mt = 0; mt < 4; mt++)
#pragma unroll
        for (int nt = 0; nt < 4; nt++)
#pragma unroll
            for (int i = 0; i < 4; i++) acc[mt][nt][i] = 0.0f;

    const int pr = tid >> 1;             // 0..127 row
    const int ps = (tid & 1) * 32;       // half-row segment (halves)

#define GPREF(p, k0)                                                           \
    do {                                                                       \
        const uint32_t ab_ = sbS + (p) * GBUF + pr * 144 + ps * 2;             \
        const __half* ga_ = A + (size_t)(bm + pr) * K + (k0) + ps;             \
        const uint32_t bb_ = sbS + 2 * GBUF + (p) * GBUF + pr * 144 + ps * 2;  \
        const __half* gb_ = Bt + (size_t)(bn + pr) * K + (k0) + ps;            \
        cpa16(ab_,      ga_);      cpa16(ab_ + 16, ga_ + 8);                   \
        cpa16(ab_ + 32, ga_ + 16); cpa16(ab_ + 48, ga_ + 24);                  \
        cpa16(bb_,      gb_);      cpa16(bb_ + 16, gb_ + 8);                   \
        cpa16(bb_ + 32, gb_ + 16); cpa16(bb_ + 48, gb_ + 24);                  \
    } while (0)

    const int NC = K >> 6;               // 64-wide chunks
    GPREF(0, 0);
    CP_COMMIT();

    for (int c = 0; c < NC; c++) {
        const int p = c & 1;
        __syncthreads();                 // prior compute on buffer p done
        if (c + 1 < NC) {
            GPREF(p ^ 1, (c + 1) * 64);
            CP_COMMIT();
            CP_WAIT(1);
        } else {
            CP_WAIT(0);
        }
        __syncthreads();

        const uint32_t po = p * GBUF;
#pragma unroll
        for (int ks = 0; ks < 4; ks++) {
            const int kb = ks * 32;      // 16 halves in bytes
            uint32_t af[4][4];
#pragma unroll
            for (int mt = 0; mt < 4; mt++)
                ldsm4(af[mt], aoff[mt] + po + kb);
#pragma unroll
            for (int nt2 = 0; nt2 < 2; nt2++) {
                uint32_t bf4[4];
                ldsm4(bf4, boff[nt2] + po + kb);
#pragma unroll
                for (int mt = 0; mt < 4; mt++) {
                    mma_f16(acc[mt][2 * nt2],     af[mt], &bf4[0]);
                    mma_f16(acc[mt][2 * nt2 + 1], af[mt], &bf4[2]);
                }
            }
        }
    }

    const int g = lane >> 2;
    const int t = lane & 3;
#pragma unroll
    for (int mt = 0; mt < 4; mt++) {
#pragma unroll
        for (int nt = 0; nt < 4; nt++) {
            const int row0 = bm + warpM * 64 + mt * 16 + g;
            const int col  = bn + warpN * 32 + nt * 8 + 2 * t;
            float c0 = alpha * acc[mt][nt][0];
            float c1 = alpha * acc[mt][nt][1];
            float c2 = alpha * acc[mt][nt][2];
            float c3 = alpha * acc[mt][nt][3];
            if (ohalf) {
                if (vtrans && col >= splitN) {
                    const int cc = col - splitN;
                    const int hidx = cc >> 6, d = cc & 63;
                    const int bb = row0 >> 12, kv = row0 & (NKV - 1);
                    __half* base = (__half*)C1 +
                        (((size_t)bb * NHEADS + hidx) * HDIM + d) * NKV + kv;
                    base[0]       = __float2half_rn(c0);
                    base[NKV]     = __float2half_rn(c1);
                    base[8]       = __float2half_rn(c2);
                    base[NKV + 8] = __float2half_rn(c3);
                } else {
                    const int ld = splitN ? splitN : N;
                    __half* dst = (__half*)C0;
                    *(uint32_t*)(dst + (size_t)row0 * ld + col)       = f2h2(c0, c1);
                    *(uint32_t*)(dst + (size_t)(row0 + 8) * ld + col) = f2h2(c2, c3);
                }
            } else {
                if (bias) {
                    const float bx = bias[col], by = bias[col + 1];
                    c0 += bx; c1 += by; c2 += bx; c3 += by;
                }
                float* dst = (float*)C0;
                float2 v0 = {c0, c1}, v1 = {c2, c3};
                *(float2*)(dst + (size_t)row0 * N + col)       = v0;
                *(float2*)(dst + (size_t)(row0 + 8) * N + col) = v1;
            }
        }
    }
}

// ---------------- flash attention: fp16 mma + cp.async double buffer -------
#define TILE_B 9216
#define ATT_SMEM (4 * TILE_B + TILE_B + 2 * 256)

__global__ __launch_bounds__(128, 3) void attn_mma(
    const __half* __restrict__ qp, const __half* __restrict__ kh,
    const __half* __restrict__ vth, const float* __restrict__ mb,
    __half* __restrict__ xout)
{
    extern __shared__ char smc[];
    const uint32_t sb = smem_u32(smc);
    const uint32_t sK0 = sb, sV0 = sb + 2 * TILE_B;
    const uint32_t sP  = sb + 4 * TILE_B;
    const uint32_t sM0 = sb + 5 * TILE_B;
    __half* Psh = (__half*)(smc + 4 * TILE_B);

    const int tid = threadIdx.x;
    const int w = tid >> 5, lane = tid & 31;
    const int g = lane >> 2, t = lane & 3;
    const int q0 = blockIdx.x * 64;
    const int hh = blockIdx.y;
    const int b  = blockIdx.z;

    const __half* qbase  = qp  + ((size_t)b * NQ + q0) * D_MODEL + hh * HDIM;
    const __half* kbase  = kh  + (size_t)b * NKV * D_MODEL + hh * HDIM;
    const __half* vtbase = vth + ((size_t)b * NHEADS + hh) * HDIM * NKV;
    const float*  mbase  = mb  + (size_t)b * NKV;

    const int lr   = lane & 7;
    const int lhi8 = ((lane >> 4) & 1) * 8;
    const int lhf  = (lane >> 3) & 1;
    uint32_t preB[4];
#pragma unroll
    for (int j2 = 0; j2 < 4; j2++)
        preB[j2] = ((j2 * 16 + lhi8 + lr) * 72 + lhf * 8) * 2;
    const uint32_t preA = ((w * 16 + (lane & 15)) * 72 + (lane >> 4) * 8) * 2;

    {
        const int r = tid >> 1, c0 = (tid & 1) * 32;
        const uint4* src = (const uint4*)(qbase + (size_t)r * D_MODEL + c0);
        uint4* dst = (uint4*)(Psh + r * 72 + c0);
#pragma unroll
        for (int i = 0; i < 4; i++) dst[i] = src[i];
    }
    __syncthreads();

    const int mrow = w * 16 + g;
    uint32_t aq[4][4];
#pragma unroll
    for (int ks = 0; ks < 4; ks++)
        ldsm4(aq[ks], sP + preA + ks * 32);

    float m_run[2] = {-1e30f, -1e30f};
    float l_run[2] = {0.0f, 0.0f};
    float o[8][4];
#pragma unroll
    for (int j = 0; j < 8; j++)
#pragma unroll
        for (int i = 0; i < 4; i++) o[j][i] = 0.0f;

#define PREFETCH(p, k0)                                                        \
    do {                                                                       \
        const uint32_t kb_ = sK0 + (p) * TILE_B;                               \
        const uint32_t vb_ = sV0 + (p) * TILE_B;                               \
        _Pragma("unroll")                                                      \
        for (int i_ = 0; i_ < 4; i_++) {                                       \
            const int c_ = tid + i_ * 128;                                     \
            const int r_ = c_ >> 3, o_ = (c_ & 7) * 8;                         \
            cpa16(kb_ + r_ * 144 + o_ * 2,                                     \
                  kbase + (size_t)((k0) + r_) * D_MODEL + o_);                 \
            cpa16(vb_ + r_ * 144 + o_ * 2,                                     \
                  vtbase + (size_t)r_ * NKV + (k0) + o_);                      \
        }                                                                      \
        if (tid < 16)                                                          \
            cpa16(sM0 + (p) * 256 + tid * 16, mbase + (k0) + tid * 4);         \
    } while (0)

    PREFETCH(0, 0);
    CP_COMMIT();

    for (int tile = 0; tile < NKV / 64; tile++) {
        const int p = tile & 1;
        __syncthreads();
        if (tile + 1 < NKV / 64) {
            PREFETCH(p ^ 1, (tile + 1) * 64);
            CP_COMMIT();
            CP_WAIT(1);
        } else {
            CP_WAIT(0);
        }
        __syncthreads();

        const uint32_t kbuf = sK0 + p * TILE_B;
        const uint32_t vbuf = sV0 + p * TILE_B;
        const float* mskb = (const float*)(smc + 5 * TILE_B + p * 256);

        float s[8][4];
#pragma unroll
        for (int j = 0; j < 8; j++)
#pragma unroll
            for (int i = 0; i < 4; i++) s[j][i] = 0.0f;

#pragma unroll
        for (int ks = 0; ks < 4; ks++) {
            const int kb = ks * 32;
#pragma unroll
            for (int j2 = 0; j2 < 4; j2++) {
                uint32_t bf4[4];
                ldsm4(bf4, kbuf + preB[j2] + kb);
                mma_f16(s[2 * j2],     aq[ks], &bf4[0]);
                mma_f16(s[2 * j2 + 1], aq[ks], &bf4[2]);
            }
        }

        float rm0 = -1e30f, rm1 = -1e30f;
#pragma unroll
        for (int j = 0; j < 8; j++) {
            const float b0 = mskb[j * 8 + 2 * t];
            const float b1 = mskb[j * 8 + 2 * t + 1];
            s[j][0] += b0; s[j][1] += b1;
            s[j][2] += b0; s[j][3] += b1;
            rm0 = fmaxf(rm0, fmaxf(s[j][0], s[j][1]));
            rm1 = fmaxf(rm1, fmaxf(s[j][2], s[j][3]));
        }
        rm0 = fmaxf(rm0, __shfl_xor_sync(0xffffffffu, rm0, 1));
        rm0 = fmaxf(rm0, __shfl_xor_sync(0xffffffffu, rm0, 2));
        rm1 = fmaxf(rm1, __shfl_xor_sync(0xffffffffu, rm1, 1));
        rm1 = fmaxf(rm1, __shfl_xor_sync(0xffffffffu, rm1, 2));

        const float mn0 = fmaxf(m_run[0], rm0);
        const float mn1 = fmaxf(m_run[1], rm1);
        const float sc0 = __expf(m_run[0] - mn0);
        const float sc1 = __expf(m_run[1] - mn1);
        float rs0 = 0.0f, rs1 = 0.0f;
#pragma unroll
        for (int j = 0; j < 8; j++) {
            s[j][0] = __expf(s[j][0] - mn0); rs0 += s[j][0];
            s[j][1] = __expf(s[j][1] - mn0); rs0 += s[j][1];
            s[j][2] = __expf(s[j][2] - mn1); rs1 += s[j][2];
            s[j][3] = __expf(s[j][3] - mn1); rs1 += s[j][3];
        }
        rs0 += __shfl_xor_sync(0xffffffffu, rs0, 1);
        rs0 += __shfl_xor_sync(0xffffffffu, rs0, 2);
        rs1 += __shfl_xor_sync(0xffffffffu, rs1, 1);
        rs1 += __shfl_xor_sync(0xffffffffu, rs1, 2);
        l_run[0] = l_run[0] * sc0 + rs0;
        l_run[1] = l_run[1] * sc1 + rs1;
        m_run[0] = mn0;
        m_run[1] = mn1;
#pragma unroll
        for (int j = 0; j < 8; j++) {
            o[j][0] *= sc0; o[j][1] *= sc0;
            o[j][2] *= sc1; o[j][3] *= sc1;
        }

#pragma unroll
        for (int j = 0; j < 8; j++) {
            *(uint32_t*)&Psh[ mrow      * 72 + j * 8 + 2 * t] = f2h2(s[j][0], s[j][1]);
            *(uint32_t*)&Psh[(mrow + 8) * 72 + j * 8 + 2 * t] = f2h2(s[j][2], s[j][3]);
        }
        __syncwarp();

#pragma unroll
        for (int ks = 0; ks < 4; ks++) {
            const int kb = ks * 32;
            uint32_t ap[4];
            ldsm4(ap, sP + preA + kb);
#pragma unroll
            for (int j2 = 0; j2 < 4; j2++) {
                uint32_t bf4[4];
                ldsm4(bf4, vbuf + preB[j2] + kb);
                mma_f16(o[2 * j2],     ap, &bf4[0]);
                mma_f16(o[2 * j2 + 1], ap, &bf4[2]);
            }
        }
        __syncwarp();
    }

    const float inv0 = 1.0f / l_run[0];
    const float inv1 = 1.0f / l_run[1];
    __half* orow0 = xout + ((size_t)b * NQ + q0 + mrow    ) * D_MODEL + hh * HDIM;
    __half* orow1 = xout + ((size_t)b * NQ + q0 + mrow + 8) * D_MODEL + hh * HDIM;
#pragma unroll
    for (int j = 0; j < 8; j++) {
        *(uint32_t*)(orow0 + j * 8 + 2 * t) = f2h2(o[j][0] * inv0, o[j][1] * inv0);
        *(uint32_t*)(orow1 + j * 8 + 2 * t) = f2h2(o[j][2] * inv1, o[j][3] * inv1);
    }
}

// ---------------- launch ----------------
extern "C" void kernel_launch(void* const* d_in, const int* in_sizes, int n_in,
                              void* d_out, int out_size) {
    const float* q     = (const float*)d_in[0];
    const float* kv    = (const float*)d_in[1];
    const void*  mask  = d_in[2];
    const float* Wq    = (const float*)d_in[3];
    const float* Wkv   = (const float*)d_in[4];
    const float* Wproj = (const float*)d_in[5];
    const float* bproj = (const float*)d_in[6];
    float* out = (float*)d_out;

    __half *qh, *kvh, *wqt, *wkvt, *wpt, *qp, *kh, *vt, *xh;
    float *mb;
    cudaGetSymbolAddress((void**)&qh,   g_qh);
    cudaGetSymbolAddress((void**)&kvh,  g_kvh);
    cudaGetSymbolAddress((void**)&wqt,  g_wqt);
    cudaGetSymbolAddress((void**)&wkvt, g_wkvt);
    cudaGetSymbolAddress((void**)&wpt,  g_wpt);
    cudaGetSymbolAddress((void**)&qp,   g_qp);
    cudaGetSymbolAddress((void**)&kh,   g_kh);
    cudaGetSymbolAddress((void**)&vt,   g_vT);
    cudaGetSymbolAddress((void**)&xh,   g_xh);
    cudaGetSymbolAddress((void**)&mb,   g_mb);

    cudaFuncSetAttribute(attn_mma,
                         cudaFuncAttributeMaxDynamicSharedMemorySize, ATT_SMEM);
    cudaFuncSetAttribute(hgemm,
                         cudaFuncAttributeMaxDynamicSharedMemorySize, HG_SMEM);

    detect_mask_kernel<<<1, 256>>>((const unsigned int*)mask);
    maskbias_kernel<<<(BATCH * NKV) / 256, 256>>>(mask);

    // convert activations + weights to half
    cvt_h_kernel<<<(BATCH * NQ  * D_MODEL) / 2048, 256>>>(q,  qh);
    cvt_h_kernel<<<(BATCH * NKV * D_MODEL) / 2048, 256>>>(kv, kvh);
    transpose_h_kernel<<<dim3(D_MODEL / 32, D_MODEL / 32), dim3(32, 8)>>>(
        Wq, wqt, D_MODEL, D_MODEL);
    transpose_h_kernel<<<dim3((2 * D_MODEL) / 32, D_MODEL / 32), dim3(32, 8)>>>(
        Wkv, wkvt, D_MODEL, 2 * D_MODEL);
    transpose_h_kernel<<<dim3(D_MODEL / 32, D_MODEL / 32), dim3(32, 8)>>>(
        Wproj, wpt, D_MODEL, D_MODEL);

    // qp = 0.125 * (q @ Wq) -> half
    hgemm<<<dim3(D_MODEL / 128, (BATCH * NQ) / 128), 256, HG_SMEM>>>(
        qh, wqt, qp, nullptr, BATCH * NQ, D_MODEL, D_MODEL, 0.125f, nullptr,
        0, 1, 0);

    // kvp = kv @ Wkv -> k half linear, v half transposed
    hgemm<<<dim3((2 * D_MODEL) / 128, (BATCH * NKV) / 128), 256, HG_SMEM>>>(
        kvh, wkvt, kh, vt, BATCH * NKV, 2 * D_MODEL, D_MODEL, 1.0f, nullptr,
        D_MODEL, 1, 1);

    // attention -> xh half
    attn_mma<<<dim3(NQ / 64, NHEADS, BATCH), 128, ATT_SMEM>>>(
        qp, kh, vt, mb, xh);

    // out = x @ Wproj + bproj (float)
    hgemm<<<dim3(D_MODEL / 128, (BATCH * NQ) / 128), 256, HG_SMEM>>>(
        xh, wpt, out, nullptr, BATCH * NQ, D_MODEL, D_MODEL, 1.0f, bproj,
        0, 0, 0);
}